// round 1
// baseline (speedup 1.0000x reference)
#include <cuda_runtime.h>
#include <cstdint>

static constexpr int NB = 8;
static constexpr int NC = 256;
static constexpr int NH = 160;
static constexpr int NW = 160;
static constexpr int NHW = NH * NW;           // 25600
static constexpr float BN_EPS = 1e-5f;

// ---------------- scratch (static device globals; no allocations) ----------
__device__ float g_xal[(size_t)NB * NC * NHW];   // aligned+BN+SiLU activations
__device__ float g_gsum[NB * NC];
__device__ float g_gmax[NB * NC];
__device__ float g_lsum[NB * NC * 16];
__device__ float g_ca[NB * NC];
__device__ float g_sf[NB * 2 * NHW];
__device__ float g_o1[NB * 16 * NHW];
__device__ float g_sampled[NB * 2 * NHW];
__device__ float g_sa[NB * NHW];
__device__ float g_wavg[2 * 16 * 9];
__device__ float g_bavg[2];

__device__ __forceinline__ float sigmoidf_(float x) {
    return 1.f / (1.f + __expf(-x));
}

// ---------------------------------------------------------------------------
// Kernel 1: 1x1 conv (GEMM 256x256 x 25600 per batch) + BN + SiLU -> g_xal
// Classic 128x128x8 SGEMM, 256 threads, 8x8 per thread.
// ---------------------------------------------------------------------------
__global__ __launch_bounds__(256) void align_gemm_kernel(
    const float* __restrict__ Wmat,   // [256,256]
    const float* __restrict__ X,      // [8,256,25600]
    const float* __restrict__ bn_g, const float* __restrict__ bn_b,
    const float* __restrict__ bn_m, const float* __restrict__ bn_v)
{
    constexpr int BM = 128, BN_ = 128, BK = 8, TM = 8, TN = 8;
    const int b = blockIdx.z;
    const int pBase = blockIdx.x * BN_;
    const int coBase = blockIdx.y * BM;
    const float* Xb = X + (size_t)b * NC * NHW;
    float* Yb = g_xal + (size_t)b * NC * NHW;

    __shared__ float As[BK][BM];
    __shared__ float Bs[BK][BN_];

    const int tid = threadIdx.x;
    const int aRow = tid >> 1;            // 0..127
    const int aCol = (tid & 1) * 4;       // 0 or 4
    const int bRow = tid >> 5;            // 0..7
    const int bCol = (tid & 31) * 4;      // 0..124
    const int tr = tid / 16;              // 0..15
    const int tc = tid % 16;              // 0..15

    float acc[TM][TN];
    #pragma unroll
    for (int i = 0; i < TM; i++)
        #pragma unroll
        for (int j = 0; j < TN; j++) acc[i][j] = 0.f;

    for (int k0 = 0; k0 < NC; k0 += BK) {
        float4 av = *reinterpret_cast<const float4*>(
            &Wmat[(coBase + aRow) * NC + k0 + aCol]);
        As[aCol + 0][aRow] = av.x;
        As[aCol + 1][aRow] = av.y;
        As[aCol + 2][aRow] = av.z;
        As[aCol + 3][aRow] = av.w;
        *reinterpret_cast<float4*>(&Bs[bRow][bCol]) =
            *reinterpret_cast<const float4*>(
                &Xb[(size_t)(k0 + bRow) * NHW + pBase + bCol]);
        __syncthreads();
        #pragma unroll
        for (int k = 0; k < BK; k++) {
            float ar[TM], br[TN];
            #pragma unroll
            for (int i = 0; i < TM; i++) ar[i] = As[k][tr * TM + i];
            #pragma unroll
            for (int j = 0; j < TN; j++) br[j] = Bs[k][tc * TN + j];
            #pragma unroll
            for (int i = 0; i < TM; i++)
                #pragma unroll
                for (int j = 0; j < TN; j++) acc[i][j] += ar[i] * br[j];
        }
        __syncthreads();
    }

    #pragma unroll
    for (int i = 0; i < TM; i++) {
        const int co = coBase + tr * TM + i;
        const float sc = bn_g[co] * rsqrtf(bn_v[co] + BN_EPS);
        const float tb = bn_b[co] - bn_m[co] * sc;
        float4 r0, r1;
        float tmp[TN];
        #pragma unroll
        for (int j = 0; j < TN; j++) {
            float y = acc[i][j] * sc + tb;
            tmp[j] = y * sigmoidf_(y);       // SiLU
        }
        r0 = make_float4(tmp[0], tmp[1], tmp[2], tmp[3]);
        r1 = make_float4(tmp[4], tmp[5], tmp[6], tmp[7]);
        float* dst = &Yb[(size_t)co * NHW + pBase + tc * TN];
        *reinterpret_cast<float4*>(dst) = r0;
        *reinterpret_cast<float4*>(dst + 4) = r1;
    }
}

// ---------------------------------------------------------------------------
// Kernel 2: per-(b,c) global sum/max + 4x4 local pool sums
// One block per (b,c), 160 threads (one per column).
// ---------------------------------------------------------------------------
__global__ __launch_bounds__(160) void pool_kernel() {
    const int bc = blockIdx.x;                  // 0..2047
    const float* p = g_xal + (size_t)bc * NHW;
    const int w = threadIdx.x;                  // 0..159
    const int gxc = w / 40;

    __shared__ float shl[16];
    __shared__ float ws[5], wm[5];
    if (threadIdx.x < 16) shl[threadIdx.x] = 0.f;
    __syncthreads();

    float s = 0.f, mx = -1e30f;
    #pragma unroll
    for (int gy = 0; gy < 4; gy++) {
        float bs = 0.f;
        for (int h = gy * 40; h < gy * 40 + 40; h++) {
            float v = p[h * NW + w];
            bs += v;
            mx = fmaxf(mx, v);
        }
        s += bs;
        atomicAdd(&shl[gy * 4 + gxc], bs);
    }
    // warp reduce
    #pragma unroll
    for (int o = 16; o > 0; o >>= 1) {
        s += __shfl_down_sync(0xffffffffu, s, o);
        mx = fmaxf(mx, __shfl_down_sync(0xffffffffu, mx, o));
    }
    const int lane = threadIdx.x & 31, wid = threadIdx.x >> 5;
    if (lane == 0) { ws[wid] = s; wm[wid] = mx; }
    __syncthreads();
    if (threadIdx.x == 0) {
        float S = 0.f, M = -1e30f;
        #pragma unroll
        for (int i = 0; i < 5; i++) { S += ws[i]; M = fmaxf(M, wm[i]); }
        g_gsum[bc] = S;
        g_gmax[bc] = M;
    }
    if (threadIdx.x < 16) g_lsum[bc * 16 + threadIdx.x] = shl[threadIdx.x];
}

// ---------------------------------------------------------------------------
// Kernel 3: pre-average offset conv2 weights over the 49 output taps
// ---------------------------------------------------------------------------
__global__ void prep_kernel(const float* __restrict__ off_w2,
                            const float* __restrict__ off_b2) {
    const int i = threadIdx.x;
    if (i < 288) {
        const int d = i / 144, rest = i % 144;
        float s = 0.f;
        for (int j = 0; j < 49; j++) s += off_w2[(d * 49 + j) * 144 + rest];
        g_wavg[i] = s * (1.f / 49.f);
    }
    if (i < 2) {
        float s = 0.f;
        for (int j = 0; j < 49; j++) s += off_b2[i * 49 + j];
        g_bavg[i] = s * (1.f / 49.f);
    }
}

// ---------------------------------------------------------------------------
// Kernel 4: channel attention -> g_ca[b, c]
// One block per batch, 256 threads.
// ---------------------------------------------------------------------------
__global__ __launch_bounds__(256) void ca_kernel(
    const float* __restrict__ mlp_w1, const float* __restrict__ mlp_w2,
    const float* __restrict__ loc_w1, const float* __restrict__ loc_w2,
    const float* __restrict__ fusion_w)
{
    const int b = blockIdx.x, tid = threadIdx.x;
    __shared__ float avg[256], mxv[256], loc[16][256];
    __shared__ float h1[32], hcell[16][16], hbar[16];

    avg[tid] = g_gsum[b * NC + tid] * (1.f / (float)NHW);
    mxv[tid] = g_gmax[b * NC + tid];
    #pragma unroll
    for (int cell = 0; cell < 16; cell++)
        loc[cell][tid] = g_lsum[(b * NC + tid) * 16 + cell] * (1.f / 1600.f);
    __syncthreads();

    if (tid < 32) {
        const int m = tid & 15;
        const float* src = (tid < 16) ? avg : mxv;
        float acc = 0.f;
        for (int c = 0; c < NC; c++) acc += mlp_w1[m * NC + c] * src[c];
        h1[tid] = fmaxf(acc, 0.f);
    }
    {
        const int cell = tid >> 4, m = tid & 15;
        float acc = 0.f;
        for (int c = 0; c < NC; c++) acc += loc_w1[m * NC + c] * loc[cell][c];
        hcell[cell][m] = fmaxf(acc, 0.f);
    }
    __syncthreads();
    if (tid < 16) {
        float s = 0.f;
        #pragma unroll
        for (int cell = 0; cell < 16; cell++) s += hcell[cell][tid];
        hbar[tid] = s * (1.f / 16.f);
    }
    __syncthreads();

    float ga = 0.f, la = 0.f;
    #pragma unroll
    for (int m = 0; m < 16; m++) {
        ga += mlp_w2[tid * 16 + m] * (h1[m] + h1[16 + m]);
        la += loc_w2[tid * 16 + m] * hbar[m];
    }
    const float alpha = sigmoidf_(fusion_w[0]);
    g_ca[b * NC + tid] = sigmoidf_(alpha * ga + (1.f - alpha) * la);
}

// ---------------------------------------------------------------------------
// Kernel 5: sf = [mean_c(ca*x), max_c(ca*x)]   (x = aligned activations)
// ---------------------------------------------------------------------------
__global__ __launch_bounds__(256) void sf_kernel() {
    const int b = blockIdx.y;
    const int p = blockIdx.x * blockDim.x + threadIdx.x;
    const float* xb = g_xal + (size_t)b * NC * NHW + p;
    const float* cab = g_ca + b * NC;
    float s = 0.f, mx = -1e30f;
    #pragma unroll 4
    for (int c = 0; c < NC; c++) {
        float v = cab[c] * xb[(size_t)c * NHW];
        s += v;
        mx = fmaxf(mx, v);
    }
    g_sf[(size_t)b * 2 * NHW + p] = s * (1.f / (float)NC);
    g_sf[(size_t)b * 2 * NHW + NHW + p] = mx;
}

// ---------------------------------------------------------------------------
// Kernel 6: offset conv1: 3x3, 2->16 + BN + ReLU
// ---------------------------------------------------------------------------
__global__ __launch_bounds__(256) void off1_kernel(
    const float* __restrict__ w1, const float* __restrict__ gg,
    const float* __restrict__ bt, const float* __restrict__ mm,
    const float* __restrict__ vv)
{
    const int p = blockIdx.x * blockDim.x + threadIdx.x;
    const int co = blockIdx.y, b = blockIdx.z;
    const int h = p / NW, w = p % NW;
    const float* sfb = g_sf + (size_t)b * 2 * NHW;
    float acc = 0.f;
    #pragma unroll
    for (int ci = 0; ci < 2; ci++) {
        #pragma unroll
        for (int ky = 0; ky < 3; ky++) {
            const int hy = h + ky - 1;
            if (hy < 0 || hy >= NH) continue;
            #pragma unroll
            for (int kx = 0; kx < 3; kx++) {
                const int wx = w + kx - 1;
                if (wx < 0 || wx >= NW) continue;
                acc += w1[((co * 2 + ci) * 3 + ky) * 3 + kx] *
                       sfb[ci * NHW + hy * NW + wx];
            }
        }
    }
    const float sc = gg[co] * rsqrtf(vv[co] + BN_EPS);
    const float tb = bt[co] - mm[co] * sc;
    g_o1[((size_t)b * 16 + co) * NHW + p] = fmaxf(acc * sc + tb, 0.f);
}

// ---------------------------------------------------------------------------
// Kernel 7: averaged offset conv2 (3x3, 16->2) + tanh*0.5 + base grid +
//           clip + bilinear grid-sample of sf -> g_sampled
// ---------------------------------------------------------------------------
__global__ __launch_bounds__(256) void off2_sample_kernel() {
    const int b = blockIdx.y;
    const int p = blockIdx.x * blockDim.x + threadIdx.x;
    const int h = p / NW, w = p % NW;
    const float* o1b = g_o1 + (size_t)b * 16 * NHW;

    float off[2];
    #pragma unroll
    for (int d = 0; d < 2; d++) {
        float acc = g_bavg[d];
        for (int ci = 0; ci < 16; ci++) {
            #pragma unroll
            for (int ky = 0; ky < 3; ky++) {
                const int hy = h + ky - 1;
                if (hy < 0 || hy >= NH) continue;
                #pragma unroll
                for (int kx = 0; kx < 3; kx++) {
                    const int wx = w + kx - 1;
                    if (wx < 0 || wx >= NW) continue;
                    acc += g_wavg[(d * 16 + ci) * 9 + ky * 3 + kx] *
                           o1b[(size_t)ci * NHW + hy * NW + wx];
                }
            }
        }
        off[d] = tanhf(acc) * 0.5f;
    }

    const float bx = -1.f + 2.f * (float)w / 159.f;
    const float by = -1.f + 2.f * (float)h / 159.f;
    const float gx = fminf(fmaxf(bx + off[0], -1.f), 1.f);
    const float gy = fminf(fmaxf(by + off[1], -1.f), 1.f);

    const float fx = (gx + 1.f) * ((float)NW * 0.5f) - 0.5f;
    const float fy = (gy + 1.f) * ((float)NH * 0.5f) - 0.5f;
    const float x0f = floorf(fx), y0f = floorf(fy);
    const int x0 = (int)x0f, y0 = (int)y0f;
    const float wx = fx - x0f, wy = fy - y0f;

    const float* sfb = g_sf + (size_t)b * 2 * NHW;
    float out0 = 0.f, out1 = 0.f;
    #pragma unroll
    for (int dy = 0; dy < 2; dy++) {
        const int yy = y0 + dy;
        if (yy < 0 || yy >= NH) continue;
        const float wgy = dy ? wy : (1.f - wy);
        #pragma unroll
        for (int dx = 0; dx < 2; dx++) {
            const int xx = x0 + dx;
            if (xx < 0 || xx >= NW) continue;
            const float wt = wgy * (dx ? wx : (1.f - wx));
            out0 += wt * sfb[yy * NW + xx];
            out1 += wt * sfb[NHW + yy * NW + xx];
        }
    }
    g_sampled[(size_t)b * 2 * NHW + p] = out0;
    g_sampled[(size_t)b * 2 * NHW + NHW + p] = out1;
}

// ---------------------------------------------------------------------------
// Kernel 8: 7x7 conv (2->1) over sampled + sigmoid -> g_sa
// ---------------------------------------------------------------------------
__global__ __launch_bounds__(256) void sa_kernel(const float* __restrict__ attn_w) {
    const int b = blockIdx.y;
    const int p = blockIdx.x * blockDim.x + threadIdx.x;
    const int h = p / NW, w = p % NW;
    const float* sm = g_sampled + (size_t)b * 2 * NHW;
    float acc = 0.f;
    #pragma unroll
    for (int ci = 0; ci < 2; ci++) {
        #pragma unroll
        for (int ky = 0; ky < 7; ky++) {
            const int hy = h + ky - 3;
            if (hy < 0 || hy >= NH) continue;
            #pragma unroll
            for (int kx = 0; kx < 7; kx++) {
                const int wx = w + kx - 3;
                if (wx < 0 || wx >= NW) continue;
                acc += attn_w[(ci * 7 + ky) * 7 + kx] *
                       sm[ci * NHW + hy * NW + wx];
            }
        }
    }
    g_sa[b * NHW + p] = sigmoidf_(acc);
}

// ---------------------------------------------------------------------------
// Kernel 9: out = sa * ca * x_aligned   (vectorized float4)
// ---------------------------------------------------------------------------
__global__ __launch_bounds__(256) void final_kernel(float* __restrict__ out) {
    const unsigned idx4 = blockIdx.x * blockDim.x + threadIdx.x;
    const unsigned total4 = (unsigned)NB * NC * NHW / 4;
    if (idx4 >= total4) return;
    const unsigned e = idx4 * 4;
    const unsigned p = e % NHW;
    const unsigned c = (e / NHW) % NC;
    const unsigned b = e / (NHW * NC);
    const float4 xv = *reinterpret_cast<const float4*>(&g_xal[e]);
    const float4 sav = *reinterpret_cast<const float4*>(&g_sa[b * NHW + p]);
    const float cc = g_ca[b * NC + c];
    float4 r;
    r.x = xv.x * sav.x * cc;
    r.y = xv.y * sav.y * cc;
    r.z = xv.z * sav.z * cc;
    r.w = xv.w * sav.w * cc;
    *reinterpret_cast<float4*>(&out[e]) = r;
}

// ---------------------------------------------------------------------------
extern "C" void kernel_launch(void* const* d_in, const int* in_sizes, int n_in,
                              void* d_out, int out_size) {
    const float* x       = (const float*)d_in[0];
    const float* align_w = (const float*)d_in[1];
    const float* align_g = (const float*)d_in[2];
    const float* align_b = (const float*)d_in[3];
    const float* align_m = (const float*)d_in[4];
    const float* align_v = (const float*)d_in[5];
    const float* mlp_w1  = (const float*)d_in[6];
    const float* mlp_w2  = (const float*)d_in[7];
    const float* loc_w1  = (const float*)d_in[8];
    const float* loc_w2  = (const float*)d_in[9];
    const float* fusion  = (const float*)d_in[10];
    const float* off_w1  = (const float*)d_in[11];
    const float* off_g   = (const float*)d_in[12];
    const float* off_bt  = (const float*)d_in[13];
    const float* off_m   = (const float*)d_in[14];
    const float* off_v   = (const float*)d_in[15];
    const float* off_w2  = (const float*)d_in[16];
    const float* off_b2  = (const float*)d_in[17];
    const float* attn_w  = (const float*)d_in[18];
    float* out = (float*)d_out;

    // 1. align GEMM + BN + SiLU
    dim3 gGemm(NHW / 128, NC / 128, NB);
    align_gemm_kernel<<<gGemm, 256>>>(align_w, x, align_g, align_b, align_m, align_v);

    // 2. channel pools
    pool_kernel<<<NB * NC, 160>>>();

    // 3. averaged offset-conv2 weights (independent)
    prep_kernel<<<1, 288>>>(off_w2, off_b2);

    // 4. channel attention
    ca_kernel<<<NB, 256>>>(mlp_w1, mlp_w2, loc_w1, loc_w2, fusion);

    // 5. spatial features (mean/max over channels of ca*x)
    dim3 gPix(NHW / 256, NB);
    sf_kernel<<<gPix, 256>>>();

    // 6. offset conv1
    dim3 gOff1(NHW / 256, 16, NB);
    off1_kernel<<<gOff1, 256>>>(off_w1, off_g, off_bt, off_m, off_v);

    // 7. offset conv2 (averaged) + grid sample
    off2_sample_kernel<<<gPix, 256>>>();

    // 8. 7x7 spatial attention conv + sigmoid
    sa_kernel<<<gPix, 256>>>(attn_w);

    // 9. final elementwise product
    const unsigned total4 = (unsigned)NB * NC * NHW / 4;
    final_kernel<<<(total4 + 255) / 256, 256>>>(out);
}